// round 7
// baseline (speedup 1.0000x reference)
#include <cuda_runtime.h>
#include <math.h>
#include <float.h>

#define BSZ 8
#define NP  1024
#define KNB 20
#define CT  169
#define EPSF 1e-6f
#define NT  8

// ---------------- scratch (device globals; no runtime allocation) ----------------
__device__ float  g_h[BSZ * 3 * NP];
__device__ float  g_xx[BSZ * NP];
__device__ float  g_dist[(size_t)BSZ * NP * NP];           // 32 MB distance matrix (L2-resident)
__device__ int    g_idx[BSZ * NP * KNB];
__device__ float  g_feat[BSZ * CT * 3 * NP];               // x1|x2|x3|x4 concat channels
__device__ float  g_p[(size_t)BSZ * NP * KNB * 85 * 3];    // 167 MB  (reused as p5)
__device__ float  g_d[(size_t)BSZ * NP * KNB * 85 * 3];    // 167 MB  (reused as d5)
__device__ double g_stats[682];
__device__ float  g_mu[341];
__device__ float  g_rstd[341];

// ---------------- kernels ----------------

__global__ void transpose_x_kernel(const float* __restrict__ x) {
    int i = blockIdx.x * blockDim.x + threadIdx.x;   // over B*N*3
    if (i >= BSZ * NP * 3) return;
    int e = i % 3;
    int n = (i / 3) % NP;
    int b = i / (3 * NP);
    g_h[(b * 3 + e) * NP + n] = x[i];
}

__global__ void xx_kernel(const float* __restrict__ f, int bstride, int D) {
    int b = blockIdx.y;
    int n = blockIdx.x * blockDim.x + threadIdx.x;
    const float* fb = f + (size_t)b * bstride;
    float s = 0.f;
    for (int d = 0; d < D; d++) {
        float v = fb[d * NP + n];
        s += v * v;
    }
    g_xx[b * NP + n] = s;
}

// pd[b][i][j] = 2*dot(f_i,f_j) - xx_i - xx_j   (== reference formula)
__global__ void knn_dist_kernel(const float* __restrict__ f, int bstride, int D) {
    __shared__ float sI[8][32];
    __shared__ float sJ[8][32];
    int b  = blockIdx.z;
    int j0 = blockIdx.x * 32;
    int i0 = blockIdx.y * 32;
    int tx = threadIdx.x, ty = threadIdx.y;
    const float* fb = f + (size_t)b * bstride;
    float acc[4] = {0.f, 0.f, 0.f, 0.f};
    for (int d0 = 0; d0 < D; d0 += 8) {
        int d = d0 + ty;
        sI[ty][tx] = (d < D) ? fb[d * NP + i0 + tx] : 0.f;
        sJ[ty][tx] = (d < D) ? fb[d * NP + j0 + tx] : 0.f;
        __syncthreads();
#pragma unroll
        for (int dd = 0; dd < 8; dd++) {
            float vj = sJ[dd][tx];
#pragma unroll
            for (int r = 0; r < 4; r++) acc[r] += sI[dd][ty + 8 * r] * vj;
        }
        __syncthreads();
    }
    float xj = g_xx[b * NP + j0 + tx];
#pragma unroll
    for (int r = 0; r < 4; r++) {
        int i = i0 + ty + 8 * r;
        g_dist[((size_t)b * NP + i) * NP + j0 + tx] = 2.f * acc[r] - g_xx[b * NP + i] - xj;
    }
}

// warp-per-row top-K via radix threshold select (register-resident, no spills).
// Selected set == jax.lax.top_k set (ties -> lowest index). Output order is
// arbitrary, which is fine: all consumers mean-pool over k.
__global__ void knn_topk_kernel() {
    int gw   = blockIdx.x * (blockDim.x >> 5) + (threadIdx.x >> 5);
    int lane = threadIdx.x & 31;
    if (gw >= BSZ * NP) return;
    const float* dr = &g_dist[(size_t)gw * NP];

    // load 32 values per lane; monotone map float -> unsigned
    unsigned u[NP / 32];
#pragma unroll
    for (int t = 0; t < NP / 32; t++) {
        unsigned bb = __float_as_uint(dr[lane + 32 * t]);
        u[t] = (bb & 0x80000000u) ? ~bb : (bb | 0x80000000u);
    }

    // binary search: largest T with count(u >= T) >= KNB  (T == 20th-largest value)
    unsigned T = 0u;
#pragma unroll
    for (int bit = 31; bit >= 0; bit--) {
        unsigned cand = T | (1u << bit);
        int c = 0;
#pragma unroll
        for (int t = 0; t < NP / 32; t++) c += (u[t] >= cand) ? 1 : 0;
        c = __reduce_add_sync(0xffffffffu, c);
        if (c >= KNB) T = cand;
    }

    // strictly-greater count (guaranteed < KNB)
    int cg = 0;
#pragma unroll
    for (int t = 0; t < NP / 32; t++) cg += (u[t] > T) ? 1 : 0;
    int totalg = __reduce_add_sync(0xffffffffu, cg);

    int* row = &g_idx[gw * KNB];
    unsigned below = (1u << lane) - 1u;
    int pos = 0;                 // write cursor for > T elements
    int quota_eq = KNB - totalg; // how many == T elements to take (ascending j)
    int eq_taken = 0;
#pragma unroll
    for (int t = 0; t < NP / 32; t++) {
        bool g = (u[t] > T), e = (u[t] == T);
        unsigned mg = __ballot_sync(0xffffffffu, g);
        unsigned me = __ballot_sync(0xffffffffu, e);
        if (g) row[pos + __popc(mg & below)] = lane + 32 * t;
        pos += __popc(mg);
        if (e) {
            int r = eq_taken + __popc(me & below);
            if (r < quota_eq) row[totalg + r] = lane + 32 * t;
        }
        eq_taken += __popc(me);
    }
}

__global__ void zero_stats_kernel() {
    int i = threadIdx.x;
    if (i < 682) g_stats[i] = 0.0;
}

// pass1: thread = (o, e).  p = Wa@nbr + (Wb-Wa)@ctr, d likewise; store p,d; norm stats
__global__ void pass1_kernel(const float* __restrict__ feat, int bstride, int C, int Cout,
                             const float* __restrict__ wf, const float* __restrict__ wd) {
    extern __shared__ float sm[];
    float* sWa   = sm;                    // Cout*C
    float* sWdel = sWa + Cout * C;
    float* sDa   = sWdel + Cout * C;
    float* sDdel = sDa + Cout * C;
    float* sCtr  = sDdel + Cout * C;      // C*3
    float* sNbr  = sCtr + C * 3;          // C*3
    float* sP    = sNbr + C * 3;          // Cout*3

    int tid = threadIdx.x;
    int b   = blockIdx.y;
    int n0  = blockIdx.x * NT;
    int o = tid / 3, e = tid % 3;
    bool act = (tid < Cout * 3);

    for (int i = tid; i < Cout * C; i += blockDim.x) {
        int oo = i / C, c = i % C;
        float a  = wf[oo * 2 * C + c];
        sWa[i]   = a;
        sWdel[i] = wf[oo * 2 * C + C + c] - a;
        float da = wd[oo * 2 * C + c];
        sDa[i]   = da;
        sDdel[i] = wd[oo * 2 * C + C + c] - da;
    }
    __syncthreads();

    const float* F = feat + (size_t)b * bstride;
    double s1 = 0.0, s2 = 0.0;

    for (int nn = 0; nn < NT; nn++) {
        int n = n0 + nn;
        __syncthreads();
        for (int i = tid; i < C * 3; i += blockDim.x) sCtr[i] = F[(size_t)i * NP + n];
        __syncthreads();
        float pc = 0.f, qc = 0.f;
        if (act) {
            const float* wr = &sWdel[o * C];
            const float* vr = &sDdel[o * C];
            for (int c = 0; c < C; c++) {
                float fv = sCtr[c * 3 + e];
                pc += wr[c] * fv;
                qc += vr[c] * fv;
            }
        }
        for (int k = 0; k < KNB; k++) {
            int j = g_idx[(b * NP + n) * KNB + k];
            __syncthreads();
            for (int i = tid; i < C * 3; i += blockDim.x) sNbr[i] = F[(size_t)i * NP + j];
            __syncthreads();
            if (act) {
                float p = pc, q = qc;
                const float* wr = &sWa[o * C];
                const float* vr = &sDa[o * C];
                for (int c = 0; c < C; c++) {
                    float fv = sNbr[c * 3 + e];
                    p += wr[c] * fv;
                    q += vr[c] * fv;
                }
                size_t base = ((((size_t)(b * NP + n)) * KNB + k) * Cout) * 3 + tid;
                g_p[base] = p;
                g_d[base] = q;
                sP[tid] = p;
            }
            __syncthreads();
            if (tid < Cout) {
                float p0 = sP[tid * 3], p1 = sP[tid * 3 + 1], p2 = sP[tid * 3 + 2];
                float nor = sqrtf(p0 * p0 + p1 * p1 + p2 * p2) + EPSF;
                s1 += (double)nor;
                s2 += (double)nor * (double)nor;
            }
        }
    }
    if (tid < Cout) {
        atomicAdd(&g_stats[tid], s1);
        atomicAdd(&g_stats[341 + tid], s2);
    }
}

__global__ void bn_finalize_kernel(int Cout, double inv_count) {
    int o = blockIdx.x * blockDim.x + threadIdx.x;
    if (o >= Cout) return;
    double mu  = g_stats[o] * inv_count;
    double var = g_stats[341 + o] * inv_count - mu * mu;
    g_mu[o]   = (float)mu;
    g_rstd[o] = (float)(1.0 / sqrt(var + 1e-5));
}

// pass2: BN + VN-LeakyReLU + mean over k -> write into concat feature buffer
__global__ void pass2_kernel(int cbase_out, int Cout,
                             const float* __restrict__ gamma, const float* __restrict__ beta) {
    int b = blockIdx.y, n = blockIdx.x;
    int o = threadIdx.x;
    if (o >= Cout) return;
    float mu = g_mu[o], rstd = g_rstd[o], gm = gamma[o], bt = beta[o];
    float a0 = 0, a1 = 0, a2 = 0;
    for (int k = 0; k < KNB; k++) {
        size_t base = ((((size_t)(b * NP + n)) * KNB + k) * Cout + o) * 3;
        float p0 = g_p[base], p1 = g_p[base + 1], p2 = g_p[base + 2];
        float d0 = g_d[base], d1 = g_d[base + 1], d2 = g_d[base + 2];
        float nor = sqrtf(p0 * p0 + p1 * p1 + p2 * p2) + EPSF;
        float s = ((nor - mu) * rstd * gm + bt) / nor;
        p0 *= s; p1 *= s; p2 *= s;
        float dot = p0 * d0 + p1 * d1 + p2 * d2;
        if (dot >= 0.f) {
            a0 += p0; a1 += p1; a2 += p2;
        } else {
            float dsq = d0 * d0 + d1 * d1 + d2 * d2;
            float f = 0.8f * dot / (dsq + EPSF);
            a0 += p0 - f * d0; a1 += p1 - f * d1; a2 += p2 - f * d2;
        }
    }
    const float inv = 1.f / (float)KNB;
    float* FO = g_feat + ((size_t)b * CT + cbase_out + o) * 3 * NP;
    FO[0 * NP + n] = a0 * inv;
    FO[1 * NP + n] = a1 * inv;
    FO[2 * NP + n] = a2 * inv;
}

// layer 5: p5[b] (341x3072) = w5 (341x169) @ feat[b] (169x3072), into g_p
__global__ void gemm_l5_kernel(const float* __restrict__ w5) {
    __shared__ float As[32][33];
    __shared__ float Bs[32][33];
    int b = blockIdx.z;
    const float* Bm = g_feat + (size_t)b * CT * 3 * NP;
    float* Cm = g_p + (size_t)b * 341 * 3072;
    int tx = threadIdx.x, ty = threadIdx.y;
    int row = blockIdx.y * 32 + ty;
    int col = blockIdx.x * 32 + tx;
    float acc = 0.f;
    for (int k0 = 0; k0 < CT; k0 += 32) {
        int ac = k0 + tx;
        As[ty][tx] = (row < 341 && ac < CT) ? w5[row * CT + ac] : 0.f;
        int br = k0 + ty;
        Bs[ty][tx] = (br < CT) ? Bm[(size_t)br * 3072 + col] : 0.f;
        __syncthreads();
#pragma unroll
        for (int q = 0; q < 32; q++) acc += As[ty][q] * Bs[q][tx];
        __syncthreads();
    }
    if (row < 341) Cm[(size_t)row * 3072 + col] = acc;
}

__global__ void d5_kernel(const float* __restrict__ wd5) {
    int i = blockIdx.x * blockDim.x + threadIdx.x;   // B*3*N
    if (i >= BSZ * 3 * NP) return;
    int n = i % NP;
    int e = (i / NP) % 3;
    int b = i / (3 * NP);
    const float* F = g_feat + (size_t)b * CT * 3 * NP;
    float a = 0.f;
    for (int c = 0; c < CT; c++) a += wd5[c] * F[(size_t)(c * 3 + e) * NP + n];
    g_d[(size_t)b * 3072 + e * NP + n] = a;
}

__global__ void stats5_kernel() {
    int o = blockIdx.x, b = blockIdx.y;
    const float* P = g_p + ((size_t)b * 341 + o) * 3072;
    double s1 = 0.0, s2 = 0.0;
    for (int n = threadIdx.x; n < NP; n += blockDim.x) {
        float p0 = P[n], p1 = P[NP + n], p2 = P[2 * NP + n];
        float nor = sqrtf(p0 * p0 + p1 * p1 + p2 * p2) + EPSF;
        s1 += (double)nor;
        s2 += (double)nor * (double)nor;
    }
#pragma unroll
    for (int off = 16; off > 0; off >>= 1) {
        s1 += __shfl_down_sync(0xffffffff, s1, off);
        s2 += __shfl_down_sync(0xffffffff, s2, off);
    }
    if ((threadIdx.x & 31) == 0) {
        atomicAdd(&g_stats[o], s1);
        atomicAdd(&g_stats[341 + o], s2);
    }
}

__global__ void pass2_l5_kernel(float* __restrict__ out,
                                const float* __restrict__ gamma, const float* __restrict__ beta) {
    int i = blockIdx.x * blockDim.x + threadIdx.x;  // over B*341*N
    if (i >= BSZ * 341 * NP) return;
    int n = i % NP;
    int o = (i / NP) % 341;
    int b = i / (341 * NP);
    const float* P = g_p + ((size_t)b * 341 + o) * 3072;
    const float* D = g_d + (size_t)b * 3072;
    float p0 = P[n], p1 = P[NP + n], p2 = P[2 * NP + n];
    float d0 = D[n], d1 = D[NP + n], d2 = D[2 * NP + n];
    float nor = sqrtf(p0 * p0 + p1 * p1 + p2 * p2) + EPSF;
    float s = ((nor - g_mu[o]) * g_rstd[o] * gamma[o] + beta[o]) / nor;
    p0 *= s; p1 *= s; p2 *= s;
    float dot = p0 * d0 + p1 * d1 + p2 * d2;
    float v0, v1, v2;
    if (dot >= 0.f) {
        v0 = p0; v1 = p1; v2 = p2;
    } else {
        float dsq = d0 * d0 + d1 * d1 + d2 * d2;
        float f = 0.8f * dot / (dsq + EPSF);
        v0 = p0 - f * d0; v1 = p1 - f * d1; v2 = p2 - f * d2;
    }
    size_t ob = ((size_t)b * 341 + o) * 3072;
    out[ob + 0 * NP + n] = v0;
    out[ob + 1 * NP + n] = v1;
    out[ob + 2 * NP + n] = v2;
}

// ---------------- launch ----------------
extern "C" void kernel_launch(void* const* d_in, const int* in_sizes, int n_in,
                              void* d_out, int out_size) {
    const float* x = (const float*)d_in[0];
    const float *W[5], *Dw[5], *G[5], *Bt[5];
    for (int l = 0; l < 5; l++) {
        W[l]  = (const float*)d_in[1 + 4 * l];
        Dw[l] = (const float*)d_in[2 + 4 * l];
        G[l]  = (const float*)d_in[3 + 4 * l];
        Bt[l] = (const float*)d_in[4 + 4 * l];
    }
    float* out = (float*)d_out;

    void* pv;
    cudaGetSymbolAddress(&pv, g_h);
    float* hptr = (float*)pv;
    cudaGetSymbolAddress(&pv, g_feat);
    float* fptr = (float*)pv;

    cudaFuncSetAttribute(pass1_kernel, cudaFuncAttributeMaxDynamicSharedMemorySize, 64 * 1024);

    transpose_x_kernel<<<96, 256>>>(x);

    struct LayerCfg { const float* feat; int D; int C; int Cout; int cbo; };
    LayerCfg L[4] = {
        { hptr,                 3,   1,  21, 0  },
        { fptr,                 63,  21, 21, 21 },
        { fptr + 21 * 3 * NP,   63,  21, 42, 42 },
        { fptr + 42 * 3 * NP,   126, 42, 85, 84 },
    };

    for (int l = 0; l < 4; l++) {
        int bstride = (l == 0) ? 3 * NP : CT * 3 * NP;
        xx_kernel<<<dim3(NP / 256, BSZ), 256>>>(L[l].feat, bstride, L[l].D);
        knn_dist_kernel<<<dim3(NP / 32, NP / 32, BSZ), dim3(32, 8)>>>(L[l].feat, bstride, L[l].D);
        knn_topk_kernel<<<BSZ * NP * 32 / 256, 256>>>();
        zero_stats_kernel<<<1, 682>>>();
        int C = L[l].C, Co = L[l].Cout;
        size_t smem = (size_t)(4 * Co * C + 2 * C * 3 + Co * 3) * sizeof(float);
        pass1_kernel<<<dim3(NP / NT, BSZ), 256, smem>>>(L[l].feat, bstride, C, Co, W[l], Dw[l]);
        bn_finalize_kernel<<<3, 128>>>(Co, 1.0 / ((double)BSZ * NP * KNB));
        pass2_kernel<<<dim3(NP, BSZ), 128>>>(L[l].cbo, Co, G[l], Bt[l]);
    }

    // layer 5
    zero_stats_kernel<<<1, 682>>>();
    gemm_l5_kernel<<<dim3(3072 / 32, (341 + 31) / 32, BSZ), dim3(32, 32)>>>(W[4]);
    d5_kernel<<<96, 256>>>(Dw[4]);
    stats5_kernel<<<dim3(341, BSZ), 256>>>();
    bn_finalize_kernel<<<3, 128>>>(341, 1.0 / ((double)BSZ * NP));
    pass2_l5_kernel<<<(BSZ * 341 * NP + 255) / 256, 256>>>(out, G[4], Bt[4]);
}

// round 9
// speedup vs baseline: 2.1888x; 2.1888x over previous
#include <cuda_runtime.h>
#include <math.h>
#include <float.h>

#define BSZ 8
#define NP  1024
#define KNB 20
#define CT  169
#define EPSF 1e-6f
#define NT  8

// ---------------- scratch (device globals; no runtime allocation) ----------------
__device__ float  g_h[BSZ * 3 * NP];
__device__ float  g_xx[BSZ * NP];
__device__ float  g_dist[(size_t)BSZ * NP * NP];           // 32 MB distance matrix (L2-resident)
__device__ int    g_idx[BSZ * NP * KNB];
__device__ float  g_feat[BSZ * CT * 3 * NP];               // x1|x2|x3|x4 concat channels
__device__ float  g_p[(size_t)BSZ * NP * KNB * 85 * 3];    // 167 MB  (reused as p5)
__device__ float  g_d[(size_t)BSZ * NP * KNB * 85 * 3];    // 167 MB  (reused as d5)
__device__ double g_stats[682];
__device__ float  g_mu[341];
__device__ float  g_rstd[341];

// ---------------- kernels ----------------

__global__ void transpose_x_kernel(const float* __restrict__ x) {
    int i = blockIdx.x * blockDim.x + threadIdx.x;   // over B*N*3
    if (i >= BSZ * NP * 3) return;
    int e = i % 3;
    int n = (i / 3) % NP;
    int b = i / (3 * NP);
    g_h[(b * 3 + e) * NP + n] = x[i];
}

__global__ void xx_kernel(const float* __restrict__ f, int bstride, int D) {
    int b = blockIdx.y;
    int n = blockIdx.x * blockDim.x + threadIdx.x;
    const float* fb = f + (size_t)b * bstride;
    float s = 0.f;
    for (int d = 0; d < D; d++) {
        float v = fb[d * NP + n];
        s += v * v;
    }
    g_xx[b * NP + n] = s;
}

// pd[b][i][j] = 2*dot(f_i,f_j) - xx_i - xx_j   (== reference formula)
__global__ void knn_dist_kernel(const float* __restrict__ f, int bstride, int D) {
    __shared__ float sI[8][32];
    __shared__ float sJ[8][32];
    int b  = blockIdx.z;
    int j0 = blockIdx.x * 32;
    int i0 = blockIdx.y * 32;
    int tx = threadIdx.x, ty = threadIdx.y;
    const float* fb = f + (size_t)b * bstride;
    float acc[4] = {0.f, 0.f, 0.f, 0.f};
    for (int d0 = 0; d0 < D; d0 += 8) {
        int d = d0 + ty;
        sI[ty][tx] = (d < D) ? fb[d * NP + i0 + tx] : 0.f;
        sJ[ty][tx] = (d < D) ? fb[d * NP + j0 + tx] : 0.f;
        __syncthreads();
#pragma unroll
        for (int dd = 0; dd < 8; dd++) {
            float vj = sJ[dd][tx];
#pragma unroll
            for (int r = 0; r < 4; r++) acc[r] += sI[dd][ty + 8 * r] * vj;
        }
        __syncthreads();
    }
    float xj = g_xx[b * NP + j0 + tx];
#pragma unroll
    for (int r = 0; r < 4; r++) {
        int i = i0 + ty + 8 * r;
        g_dist[((size_t)b * NP + i) * NP + j0 + tx] = 2.f * acc[r] - g_xx[b * NP + i] - xj;
    }
}

// warp-per-row top-K via radix threshold select (register-resident, no spills).
// Selected set == jax.lax.top_k set (ties -> lowest index). Output order is
// arbitrary, which is fine: all consumers mean-pool over k.
__global__ void knn_topk_kernel() {
    int gw   = blockIdx.x * (blockDim.x >> 5) + (threadIdx.x >> 5);
    int lane = threadIdx.x & 31;
    if (gw >= BSZ * NP) return;
    const float* dr = &g_dist[(size_t)gw * NP];

    unsigned u[NP / 32];
#pragma unroll
    for (int t = 0; t < NP / 32; t++) {
        unsigned bb = __float_as_uint(dr[lane + 32 * t]);
        u[t] = (bb & 0x80000000u) ? ~bb : (bb | 0x80000000u);
    }

    unsigned T = 0u;
#pragma unroll
    for (int bit = 31; bit >= 0; bit--) {
        unsigned cand = T | (1u << bit);
        int c = 0;
#pragma unroll
        for (int t = 0; t < NP / 32; t++) c += (u[t] >= cand) ? 1 : 0;
        c = __reduce_add_sync(0xffffffffu, c);
        if (c >= KNB) T = cand;
    }

    int cg = 0;
#pragma unroll
    for (int t = 0; t < NP / 32; t++) cg += (u[t] > T) ? 1 : 0;
    int totalg = __reduce_add_sync(0xffffffffu, cg);

    int* row = &g_idx[gw * KNB];
    unsigned below = (1u << lane) - 1u;
    int pos = 0;
    int quota_eq = KNB - totalg;
    int eq_taken = 0;
#pragma unroll
    for (int t = 0; t < NP / 32; t++) {
        bool g = (u[t] > T), e = (u[t] == T);
        unsigned mg = __ballot_sync(0xffffffffu, g);
        unsigned me = __ballot_sync(0xffffffffu, e);
        if (g) row[pos + __popc(mg & below)] = lane + 32 * t;
        pos += __popc(mg);
        if (e) {
            int r = eq_taken + __popc(me & below);
            if (r < quota_eq) row[totalg + r] = lane + 32 * t;
        }
        eq_taken += __popc(me);
    }
}

__global__ void zero_stats_kernel() {
    int i = threadIdx.x;
    if (i < 682) g_stats[i] = 0.0;
}

// pass1 v2: thread = (o, e), 20 k-accumulators in registers.
// Per point: load ctr + all 20 nbr features to shared (3 syncs total), then a
// single c-loop with full k-ILP: 2 weight LDS (conflict-free) + 20 broadcast
// LDS + 40 FMA per c. Stores p,d coalesced; norm stats via one shared stage.
__global__ void __launch_bounds__(256) pass1_kernel(
        const float* __restrict__ feat, int bstride, int C, int Cout,
        const float* __restrict__ wf, const float* __restrict__ wd) {
    extern __shared__ float sm[];
    float* sWa   = sm;                      // Cout*C
    float* sWdel = sWa + Cout * C;
    float* sDa   = sWdel + Cout * C;
    float* sDdel = sDa + Cout * C;
    float* sCtr  = sDdel + Cout * C;        // C*3
    float* sNbr  = sCtr + C * 3;            // KNB * C*3
    float* sP    = sNbr + KNB * C * 3;      // KNB * Cout*3

    int tid = threadIdx.x;
    int b   = blockIdx.y;
    int n0  = blockIdx.x * NT;
    int o = tid / 3, e = tid % 3;
    bool act = (tid < Cout * 3);
    int C3 = C * 3;

    for (int i = tid; i < Cout * C; i += blockDim.x) {
        int oo = i / C, c = i % C;
        float a  = wf[oo * 2 * C + c];
        sWa[i]   = a;
        sWdel[i] = wf[oo * 2 * C + C + c] - a;
        float da = wd[oo * 2 * C + c];
        sDa[i]   = da;
        sDdel[i] = wd[oo * 2 * C + C + c] - da;
    }

    const float* F = feat + (size_t)b * bstride;
    const int* idxr0 = &g_idx[(b * NP + n0) * KNB];
    double s1 = 0.0, s2 = 0.0;

    for (int nn = 0; nn < NT; nn++) {
        int n = n0 + nn;
        const int* idxr = idxr0 + nn * KNB;
        __syncthreads();   // prior iter's stats (sP) and compute (sNbr) complete
        for (int i = tid; i < C3; i += blockDim.x) sCtr[i] = F[(size_t)i * NP + n];
        for (int i = tid; i < KNB * C3; i += blockDim.x) {
            int k = i / C3, r = i - k * C3;
            int j = idxr[k];                    // tiny row, L1-resident
            sNbr[i] = F[(size_t)r * NP + j];
        }
        __syncthreads();

        if (act) {
            float accP[KNB], accQ[KNB];
            // center contribution (shared across k)
            float pc = 0.f, qc = 0.f;
            const float* wrD = &sWdel[o * C];
            const float* vrD = &sDdel[o * C];
            for (int c = 0; c < C; c++) {
                float fv = sCtr[c * 3 + e];
                pc += wrD[c] * fv;
                qc += vrD[c] * fv;
            }
#pragma unroll
            for (int k = 0; k < KNB; k++) { accP[k] = pc; accQ[k] = qc; }

            const float* wr = &sWa[o * C];
            const float* vr = &sDa[o * C];
            for (int c = 0; c < C; c++) {
                float w = wr[c], v = vr[c];
                const float* nb = &sNbr[c * 3 + e];
#pragma unroll
                for (int k = 0; k < KNB; k++) {
                    float fv = nb[k * C3];
                    accP[k] += w * fv;
                    accQ[k] += v * fv;
                }
            }
            size_t base0 = (((size_t)(b * NP + n)) * KNB) * Cout * 3 + tid;
#pragma unroll
            for (int k = 0; k < KNB; k++) {
                size_t base = base0 + (size_t)k * Cout * 3;
                g_p[base] = accP[k];
                g_d[base] = accQ[k];
                sP[k * Cout * 3 + tid] = accP[k];
            }
        }
        __syncthreads();
        if (tid < Cout) {
#pragma unroll
            for (int k = 0; k < KNB; k++) {
                const float* pp = &sP[k * Cout * 3 + tid * 3];
                float nor = sqrtf(pp[0] * pp[0] + pp[1] * pp[1] + pp[2] * pp[2]) + EPSF;
                s1 += (double)nor;
                s2 += (double)nor * (double)nor;
            }
        }
    }
    if (tid < Cout) {
        atomicAdd(&g_stats[tid], s1);
        atomicAdd(&g_stats[341 + tid], s2);
    }
}

__global__ void bn_finalize_kernel(int Cout, double inv_count) {
    int o = blockIdx.x * blockDim.x + threadIdx.x;
    if (o >= Cout) return;
    double mu  = g_stats[o] * inv_count;
    double var = g_stats[341 + o] * inv_count - mu * mu;
    g_mu[o]   = (float)mu;
    g_rstd[o] = (float)(1.0 / sqrt(var + 1e-5));
}

// pass2: BN + VN-LeakyReLU + mean over k -> write into concat feature buffer
__global__ void pass2_kernel(int cbase_out, int Cout,
                             const float* __restrict__ gamma, const float* __restrict__ beta) {
    int b = blockIdx.y, n = blockIdx.x;
    int o = threadIdx.x;
    if (o >= Cout) return;
    float mu = g_mu[o], rstd = g_rstd[o], gm = gamma[o], bt = beta[o];
    float a0 = 0, a1 = 0, a2 = 0;
    for (int k = 0; k < KNB; k++) {
        size_t base = ((((size_t)(b * NP + n)) * KNB + k) * Cout + o) * 3;
        float p0 = g_p[base], p1 = g_p[base + 1], p2 = g_p[base + 2];
        float d0 = g_d[base], d1 = g_d[base + 1], d2 = g_d[base + 2];
        float nor = sqrtf(p0 * p0 + p1 * p1 + p2 * p2) + EPSF;
        float s = ((nor - mu) * rstd * gm + bt) / nor;
        p0 *= s; p1 *= s; p2 *= s;
        float dot = p0 * d0 + p1 * d1 + p2 * d2;
        if (dot >= 0.f) {
            a0 += p0; a1 += p1; a2 += p2;
        } else {
            float dsq = d0 * d0 + d1 * d1 + d2 * d2;
            float f = 0.8f * dot / (dsq + EPSF);
            a0 += p0 - f * d0; a1 += p1 - f * d1; a2 += p2 - f * d2;
        }
    }
    const float inv = 1.f / (float)KNB;
    float* FO = g_feat + ((size_t)b * CT + cbase_out + o) * 3 * NP;
    FO[0 * NP + n] = a0 * inv;
    FO[1 * NP + n] = a1 * inv;
    FO[2 * NP + n] = a2 * inv;
}

// layer 5: p5[b] (341x3072) = w5 (341x169) @ feat[b] (169x3072), into g_p
// 64x64 tile, 4x4 register micro-tile per thread (16x16 threads).
__global__ void __launch_bounds__(256) gemm_l5_kernel(const float* __restrict__ w5) {
    __shared__ float As[64][17];     // [m][k]
    __shared__ float Bs[16][64];     // [k][n]
    int b = blockIdx.z;
    const float* Bm = g_feat + (size_t)b * CT * 3 * NP;
    float* Cm = g_p + (size_t)b * 341 * 3072;
    int tid = threadIdx.x;
    int tx = tid & 15, ty = tid >> 4;
    int m0 = blockIdx.y * 64;
    int n0 = blockIdx.x * 64;
    float acc[4][4] = {};
    for (int k0 = 0; k0 < CT; k0 += 16) {
        // As: 64 m x 16 k; consecutive tid -> consecutive k (coalesced gmem)
        for (int i = tid; i < 64 * 16; i += 256) {
            int k = i & 15, m = i >> 4;
            int gm_ = m0 + m, gk = k0 + k;
            As[m][k] = (gm_ < 341 && gk < CT) ? w5[gm_ * CT + gk] : 0.f;
        }
        // Bs: 16 k x 64 n; consecutive tid -> consecutive n (coalesced gmem)
        for (int i = tid; i < 16 * 64; i += 256) {
            int nn = i & 63, k = i >> 6;
            int gk = k0 + k;
            Bs[k][nn] = (gk < CT) ? Bm[(size_t)gk * 3072 + n0 + nn] : 0.f;
        }
        __syncthreads();
#pragma unroll
        for (int kk = 0; kk < 16; kk++) {
            float a0 = As[ty * 4 + 0][kk];
            float a1 = As[ty * 4 + 1][kk];
            float a2 = As[ty * 4 + 2][kk];
            float a3 = As[ty * 4 + 3][kk];
            float b0 = Bs[kk][tx * 4 + 0];
            float b1 = Bs[kk][tx * 4 + 1];
            float b2 = Bs[kk][tx * 4 + 2];
            float b3 = Bs[kk][tx * 4 + 3];
            acc[0][0] += a0 * b0; acc[0][1] += a0 * b1; acc[0][2] += a0 * b2; acc[0][3] += a0 * b3;
            acc[1][0] += a1 * b0; acc[1][1] += a1 * b1; acc[1][2] += a1 * b2; acc[1][3] += a1 * b3;
            acc[2][0] += a2 * b0; acc[2][1] += a2 * b1; acc[2][2] += a2 * b2; acc[2][3] += a2 * b3;
            acc[3][0] += a3 * b0; acc[3][1] += a3 * b1; acc[3][2] += a3 * b2; acc[3][3] += a3 * b3;
        }
        __syncthreads();
    }
#pragma unroll
    for (int r = 0; r < 4; r++) {
        int gm_ = m0 + ty * 4 + r;
        if (gm_ < 341) {
#pragma unroll
            for (int s = 0; s < 4; s++)
                Cm[(size_t)gm_ * 3072 + n0 + tx * 4 + s] = acc[r][s];
        }
    }
}

__global__ void d5_kernel(const float* __restrict__ wd5) {
    int i = blockIdx.x * blockDim.x + threadIdx.x;   // B*3*N
    if (i >= BSZ * 3 * NP) return;
    int n = i % NP;
    int e = (i / NP) % 3;
    int b = i / (3 * NP);
    const float* F = g_feat + (size_t)b * CT * 3 * NP;
    float a = 0.f;
    for (int c = 0; c < CT; c++) a += wd5[c] * F[(size_t)(c * 3 + e) * NP + n];
    g_d[(size_t)b * 3072 + e * NP + n] = a;
}

__global__ void stats5_kernel() {
    int o = blockIdx.x, b = blockIdx.y;
    const float* P = g_p + ((size_t)b * 341 + o) * 3072;
    double s1 = 0.0, s2 = 0.0;
    for (int n = threadIdx.x; n < NP; n += blockDim.x) {
        float p0 = P[n], p1 = P[NP + n], p2 = P[2 * NP + n];
        float nor = sqrtf(p0 * p0 + p1 * p1 + p2 * p2) + EPSF;
        s1 += (double)nor;
        s2 += (double)nor * (double)nor;
    }
#pragma unroll
    for (int off = 16; off > 0; off >>= 1) {
        s1 += __shfl_down_sync(0xffffffff, s1, off);
        s2 += __shfl_down_sync(0xffffffff, s2, off);
    }
    if ((threadIdx.x & 31) == 0) {
        atomicAdd(&g_stats[o], s1);
        atomicAdd(&g_stats[341 + o], s2);
    }
}

__global__ void pass2_l5_kernel(float* __restrict__ out,
                                const float* __restrict__ gamma, const float* __restrict__ beta) {
    int i = blockIdx.x * blockDim.x + threadIdx.x;  // over B*341*N
    if (i >= BSZ * 341 * NP) return;
    int n = i % NP;
    int o = (i / NP) % 341;
    int b = i / (341 * NP);
    const float* P = g_p + ((size_t)b * 341 + o) * 3072;
    const float* D = g_d + (size_t)b * 3072;
    float p0 = P[n], p1 = P[NP + n], p2 = P[2 * NP + n];
    float d0 = D[n], d1 = D[NP + n], d2 = D[2 * NP + n];
    float nor = sqrtf(p0 * p0 + p1 * p1 + p2 * p2) + EPSF;
    float s = ((nor - g_mu[o]) * g_rstd[o] * gamma[o] + beta[o]) / nor;
    p0 *= s; p1 *= s; p2 *= s;
    float dot = p0 * d0 + p1 * d1 + p2 * d2;
    float v0, v1, v2;
    if (dot >= 0.f) {
        v0 = p0; v1 = p1; v2 = p2;
    } else {
        float dsq = d0 * d0 + d1 * d1 + d2 * d2;
        float f = 0.8f * dot / (dsq + EPSF);
        v0 = p0 - f * d0; v1 = p1 - f * d1; v2 = p2 - f * d2;
    }
    size_t ob = ((size_t)b * 341 + o) * 3072;
    out[ob + 0 * NP + n] = v0;
    out[ob + 1 * NP + n] = v1;
    out[ob + 2 * NP + n] = v2;
}

// ---------------- launch ----------------
extern "C" void kernel_launch(void* const* d_in, const int* in_sizes, int n_in,
                              void* d_out, int out_size) {
    const float* x = (const float*)d_in[0];
    const float *W[5], *Dw[5], *G[5], *Bt[5];
    for (int l = 0; l < 5; l++) {
        W[l]  = (const float*)d_in[1 + 4 * l];
        Dw[l] = (const float*)d_in[2 + 4 * l];
        G[l]  = (const float*)d_in[3 + 4 * l];
        Bt[l] = (const float*)d_in[4 + 4 * l];
    }
    float* out = (float*)d_out;

    void* pv;
    cudaGetSymbolAddress(&pv, g_h);
    float* hptr = (float*)pv;
    cudaGetSymbolAddress(&pv, g_feat);
    float* fptr = (float*)pv;

    cudaFuncSetAttribute(pass1_kernel, cudaFuncAttributeMaxDynamicSharedMemorySize, 100 * 1024);

    transpose_x_kernel<<<96, 256>>>(x);

    struct LayerCfg { const float* feat; int D; int C; int Cout; int cbo; };
    LayerCfg L[4] = {
        { hptr,                 3,   1,  21, 0  },
        { fptr,                 63,  21, 21, 21 },
        { fptr + 21 * 3 * NP,   63,  21, 42, 42 },
        { fptr + 42 * 3 * NP,   126, 42, 85, 84 },
    };

    for (int l = 0; l < 4; l++) {
        int bstride = (l == 0) ? 3 * NP : CT * 3 * NP;
        xx_kernel<<<dim3(NP / 256, BSZ), 256>>>(L[l].feat, bstride, L[l].D);
        knn_dist_kernel<<<dim3(NP / 32, NP / 32, BSZ), dim3(32, 8)>>>(L[l].feat, bstride, L[l].D);
        knn_topk_kernel<<<BSZ * NP * 32 / 256, 256>>>();
        zero_stats_kernel<<<1, 682>>>();
        int C = L[l].C, Co = L[l].Cout;
        size_t smem = (size_t)(4 * Co * C + C * 3 + KNB * C * 3 + KNB * Co * 3) * sizeof(float);
        pass1_kernel<<<dim3(NP / NT, BSZ), 256, smem>>>(L[l].feat, bstride, C, Co, W[l], Dw[l]);
        bn_finalize_kernel<<<3, 128>>>(Co, 1.0 / ((double)BSZ * NP * KNB));
        int p2threads = ((Co + 31) / 32) * 32;
        pass2_kernel<<<dim3(NP, BSZ), p2threads>>>(L[l].cbo, Co, G[l], Bt[l]);
    }

    // layer 5
    zero_stats_kernel<<<1, 682>>>();
    gemm_l5_kernel<<<dim3(3072 / 64, (341 + 63) / 64, BSZ), 256>>>(W[4]);
    d5_kernel<<<96, 256>>>(Dw[4]);
    stats5_kernel<<<dim3(341, BSZ), 256>>>();
    bn_finalize_kernel<<<3, 128>>>(341, 1.0 / ((double)BSZ * NP));
    pass2_l5_kernel<<<(BSZ * 341 * NP + 255) / 256, 256>>>(out, G[4], Bt[4]);
}